// round 15
// baseline (speedup 1.0000x reference)
#include <cuda_runtime.h>
#include <math_constants.h>

#define Bz 8
#define Cc 64
#define Nn 2048
#define Mm 2048
#define KTH 613            // index of (int(2048*0.3))-th smallest

#define OFF_CORR 0
#define OFF_SW   (Bz*3*Nn)
#define OFF_MS   (OFF_SW + Bz*Nn)
#define OFF_MT   (OFF_MS + Bz*Nn)

// ---------------- scratch ----------------
__device__ __align__(16) float g_pd[(size_t)Bz*Nn*Mm];   // pd, overwritten with E=exp(pd-rowmax) by k_sums
__device__ float g_xx[Bz*Nn];
__device__ float g_yy[Bz*Mm];
__device__ float g_rmax_p[(size_t)Bz*16*Nn];
__device__ float g_cmax_p[(size_t)Bz*16*Mm];
__device__ float g_rowmax[Bz*Nn];
__device__ float g_colmax[Bz*Mm];
__device__ float g_C[Bz];                      // per-batch reference: max_n rowmax
__device__ float g_rsum_p[(size_t)Bz*16*Nn];
__device__ float g_csum_p[(size_t)Bz*32*Mm];   // sum of E*f_n partials
__device__ float g_rowinv[Bz*Nn];              // 1/rowsum; == topk (K=1)
__device__ float g_colinv[Bz*Mm];
__device__ float g_frow[Bz*Nn];                // exp(rowmax - C)
__device__ float g_gcol[Bz*Mm];                // exp(C - colmax) * colinv
__device__ float g_rs_p[(size_t)Bz*16*Nn];
__device__ float g_cs_p[(size_t)Bz*32*Mm];
__device__ float g_rowscore[Bz*Nn];
__device__ __align__(16) float g_colscore[Bz*Mm];
__device__ float g_rowth[Bz], g_colth[Bz];
__device__ float g_valsum[Bz*Nn];

// ---------------- block reductions (blockDim.x == 256) ----------------
__device__ __forceinline__ float bsum256(float v, float* red) {
    int t = threadIdx.x;
    __syncthreads();
    red[t] = v; __syncthreads();
#pragma unroll
    for (int s = 128; s > 0; s >>= 1) {
        if (t < s) red[t] += red[t + s];
        __syncthreads();
    }
    return red[0];
}

// ---------------- K0: squared norms ----------------
__global__ void k_sq(const float* __restrict__ A, int cols, int which) {
    int idx = blockIdx.x * 256 + threadIdx.x;
    if (idx >= Bz * cols) return;
    int b = idx / cols, x = idx % cols;
    const float* p = A + (size_t)b * Cc * cols + x;
    float s = 0.f;
#pragma unroll
    for (int c = 0; c < Cc; c++) { float v = p[(size_t)c * cols]; s += v * v; }
    (which ? g_yy : g_xx)[idx] = s;
}

// ---------------- K1: GEMM 128x128 tile, 8x8/thread; store pd + row/col max partials ----------------
__global__ __launch_bounds__(256) void k_gemm(const float* __restrict__ A, const float* __restrict__ Bt) {
    __shared__ float As[32][128];
    __shared__ float Bs[32][128];
    __shared__ float rbuf[128][17];
    int b = blockIdx.z;
    int n0 = blockIdx.y * 128, m0 = blockIdx.x * 128;
    const float* Ab = A  + (size_t)b * Cc * Nn + n0;
    const float* Bb = Bt + (size_t)b * Cc * Mm + m0;
    int t = threadIdx.x;
    int tx = t & 15, ty = t >> 4;

    __align__(16) float acc[8][8];
#pragma unroll
    for (int i = 0; i < 8; i++)
#pragma unroll
        for (int j = 0; j < 8; j++) acc[i][j] = 0.f;

#pragma unroll
    for (int ks = 0; ks < 64; ks += 32) {
#pragma unroll
        for (int k = 0; k < 4; k++) {
            int f = t + k * 256;
            int c = f >> 5;
            int p = (f & 31) << 2;
            float4 av  = *(const float4*)&Ab[(size_t)(ks + c) * Nn + p];
            float4 bvv = *(const float4*)&Bb[(size_t)(ks + c) * Mm + p];
            As[c][p] = av.x; As[c][p+1] = av.y; As[c][p+2] = av.z; As[c][p+3] = av.w;
            Bs[c][p] = bvv.x; Bs[c][p+1] = bvv.y; Bs[c][p+2] = bvv.z; Bs[c][p+3] = bvv.w;
        }
        __syncthreads();
#pragma unroll
        for (int c = 0; c < 32; c++) {
            float a[8], bv[8];
#pragma unroll
            for (int i = 0; i < 8; i++) { a[i] = As[c][ty * 8 + i]; bv[i] = Bs[c][tx * 8 + i]; }
#pragma unroll
            for (int i = 0; i < 8; i++)
#pragma unroll
                for (int j = 0; j < 8; j++) acc[i][j] += a[i] * bv[j];
        }
        __syncthreads();
    }

    float xs[8], ys[8];
#pragma unroll
    for (int i = 0; i < 8; i++) xs[i] = g_xx[b * Nn + n0 + ty * 8 + i];
#pragma unroll
    for (int j = 0; j < 8; j++) ys[j] = g_yy[b * Mm + m0 + tx * 8 + j];

#pragma unroll
    for (int i = 0; i < 8; i++) {
#pragma unroll
        for (int j = 0; j < 8; j++) acc[i][j] = 2.f * acc[i][j] - xs[i] - ys[j];
        size_t off = ((size_t)b * Nn + n0 + ty * 8 + i) * Mm + m0 + tx * 8;
        *(float4*)&g_pd[off]     = *(float4*)&acc[i][0];
        *(float4*)&g_pd[off + 4] = *(float4*)&acc[i][4];
    }

    // row-max partials
#pragma unroll
    for (int i = 0; i < 8; i++) {
        float mx = acc[i][0];
#pragma unroll
        for (int j = 1; j < 8; j++) mx = fmaxf(mx, acc[i][j]);
        rbuf[ty * 8 + i][tx] = mx;
    }
    __syncthreads();
    if (t < 128) {
        float mx = rbuf[t][0];
#pragma unroll
        for (int k = 1; k < 16; k++) mx = fmaxf(mx, rbuf[t][k]);
        g_rmax_p[((size_t)b * 16 + blockIdx.x) * Nn + n0 + t] = mx;
    }
    __syncthreads();
    // col-max partials
#pragma unroll
    for (int j = 0; j < 8; j++) {
        float mx = acc[0][j];
#pragma unroll
        for (int i = 1; i < 8; i++) mx = fmaxf(mx, acc[i][j]);
        rbuf[tx * 8 + j][ty] = mx;
    }
    __syncthreads();
    if (t < 128) {
        float mx = rbuf[t][0];
#pragma unroll
        for (int k = 1; k < 16; k++) mx = fmaxf(mx, rbuf[t][k]);
        g_cmax_p[((size_t)b * 16 + blockIdx.y) * Mm + m0 + t] = mx;
    }
}

// ---------------- K2: combine max partials ----------------
__global__ void k_combine1() {
    int idx = blockIdx.x * 256 + threadIdx.x;
    if (idx < Bz * Nn) {
        int b = idx / Nn, n = idx % Nn;
        float mx = -CUDART_INF_F;
#pragma unroll
        for (int k = 0; k < 16; k++) mx = fmaxf(mx, g_rmax_p[((size_t)b * 16 + k) * Nn + n]);
        g_rowmax[idx] = mx;
    } else if (idx < 2 * Bz * Nn) {
        int j = idx - Bz * Nn;
        int b = j / Mm, m = j % Mm;
        float mx = -CUDART_INF_F;
#pragma unroll
        for (int k = 0; k < 16; k++) mx = fmaxf(mx, g_cmax_p[((size_t)b * 16 + k) * Mm + m]);
        g_colmax[j] = mx;
    }
}

// ---------------- K2b: per-batch reference C = max_n rowmax ----------------
__global__ void k_cref() {
    int b = blockIdx.x, t = threadIdx.x;  // 1024
    __shared__ float red[1024];
    red[t] = fmaxf(g_rowmax[b * Nn + t], g_rowmax[b * Nn + t + 1024]);
    __syncthreads();
#pragma unroll
    for (int s = 512; s > 0; s >>= 1) {
        if (t < s) red[t] = fmaxf(red[t], red[t + s]);
        __syncthreads();
    }
    if (t == 0) g_C[b] = red[0];
}

// ---------------- K3: ONE exp/element: E=exp(pd-rowmax) written in-place; rowsum & colsum partials ----------------
__global__ __launch_bounds__(256) void k_sums() {
    __shared__ float Es[64][133];
    __shared__ float rmx[64], fr[64];
    int b = blockIdx.z, mt = blockIdx.x, nt = blockIdx.y;
    int n0 = nt * 64, m0 = mt * 128;
    int t = threadIdx.x;
    float* base = g_pd + ((size_t)b * Nn + n0) * Mm + m0;

    if (t < 64) rmx[t] = g_rowmax[b * Nn + n0 + t];
    __syncthreads();
    if (t < 64) fr[t] = expf(rmx[t] - g_C[b]);

    __align__(16) float4 ev[8];
#pragma unroll
    for (int k = 0; k < 8; k++) {
        int f = t + k * 256;
        int r = f >> 5, p = (f & 31) << 2;
        float4 v = *(const float4*)&base[(size_t)r * Mm + p];
        float m = rmx[r];
        float4 e;
        e.x = expf(v.x - m); e.y = expf(v.y - m);
        e.z = expf(v.z - m); e.w = expf(v.w - m);
        ev[k] = e;
        Es[r][p] = e.x; Es[r][p+1] = e.y; Es[r][p+2] = e.z; Es[r][p+3] = e.w;
    }
    __syncthreads();
    if (t < 64) {
        float s = 0.f;
#pragma unroll 8
        for (int j = 0; j < 128; j++) s += Es[t][j];
        g_rsum_p[((size_t)b * 16 + mt) * Nn + n0 + t] = s;
    } else if (t < 192) {
        int c = t - 64;
        float s = 0.f;
#pragma unroll 8
        for (int i = 0; i < 64; i++) s += Es[i][c] * fr[i];
        g_csum_p[((size_t)b * 32 + nt) * Mm + m0 + c] = s;
    }
    // write E back in place (tile-exclusive; same addresses as the load)
#pragma unroll
    for (int k = 0; k < 8; k++) {
        int f = t + k * 256;
        int r = f >> 5, p = (f & 31) << 2;
        *(float4*)&base[(size_t)r * Mm + p] = ev[k];
    }
}

// ---------------- K4: combine sums -> rowinv, colinv, frow, gcol ----------------
__global__ void k_combine2() {
    int idx = blockIdx.x * 256 + threadIdx.x;
    if (idx < Bz * Nn) {
        int b = idx / Nn, n = idx % Nn;
        float s = 0.f;
#pragma unroll
        for (int k = 0; k < 16; k++) s += g_rsum_p[((size_t)b * 16 + k) * Nn + n];
        g_rowinv[idx] = 1.f / s;                       // rowsum >= 1
        g_frow[idx] = expf(g_rowmax[idx] - g_C[b]);
    } else if (idx < 2 * Bz * Nn) {
        int j = idx - Bz * Nn;
        int b = j / Mm, m = j % Mm;
        float s = 0.f;
#pragma unroll
        for (int k = 0; k < 32; k++) s += g_csum_p[((size_t)b * 32 + k) * Mm + m];
        float ex = expf(g_C[b] - g_colmax[j]);         // >= 1, bounded
        float colsum = ex * s;                         // true colsum >= 1
        float ci = 1.f / colsum;
        g_colinv[j] = ci;
        g_gcol[j] = ex * ci;
    }
}

// ---------------- K5: pure-FMA pass over E -> rowScore & colScore partials ----------------
__global__ __launch_bounds__(256) void k_scores() {
    __shared__ float Es[64][133];
    __shared__ float fr[64], ri[64];
    __shared__ float gc[128];
    int b = blockIdx.z, mt = blockIdx.x, nt = blockIdx.y;
    int n0 = nt * 64, m0 = mt * 128;
    int t = threadIdx.x;
    const float* base = g_pd + ((size_t)b * Nn + n0) * Mm + m0;
#pragma unroll
    for (int k = 0; k < 8; k++) {
        int f = t + k * 256;
        int r = f >> 5, p = (f & 31) << 2;
        float4 v = *(const float4*)&base[(size_t)r * Mm + p];
        Es[r][p] = v.x; Es[r][p+1] = v.y; Es[r][p+2] = v.z; Es[r][p+3] = v.w;
    }
    if (t < 128) gc[t] = g_gcol[b * Mm + m0 + t];
    else if (t < 192) {
        int r = t - 128;
        fr[r] = g_frow[b * Nn + n0 + r];
        ri[r] = g_rowinv[b * Nn + n0 + r];
    }
    __syncthreads();
    if (t < 64) {
        // scoresRowSum_n partial = f_n * sum_m E*gcol_m
        float s = 0.f;
#pragma unroll 8
        for (int j = 0; j < 128; j++) s += Es[t][j] * gc[j];
        g_rs_p[((size_t)b * 16 + mt) * Nn + n0 + t] = fr[t] * s;
    } else if (t < 192) {
        // scoresColSum_m partial = sum_n E*rowinv_n
        int c = t - 64;
        float s = 0.f;
#pragma unroll 8
        for (int i = 0; i < 64; i++) s += Es[i][c] * ri[i];
        g_cs_p[((size_t)b * 32 + nt) * Mm + m0 + c] = s;
    }
}

// ---------------- K6: combine score partials + exact kth smallest (bitonic) ----------------
__global__ void k_thresh() {
    int b = blockIdx.x >> 1, which = blockIdx.x & 1;
    __shared__ float d[2048];
    int t = threadIdx.x;  // 1024
    if (which == 0) {
        for (int i = t; i < 2048; i += 1024) {
            float s = 0.f;
#pragma unroll
            for (int k = 0; k < 32; k++) s += g_cs_p[((size_t)b * 32 + k) * Mm + i];
            g_colscore[b * Mm + i] = s; d[i] = s;
        }
    } else {
        for (int i = t; i < 2048; i += 1024) {
            float s = 0.f;
#pragma unroll
            for (int k = 0; k < 16; k++) s += g_rs_p[((size_t)b * 16 + k) * Nn + i];
            g_rowscore[b * Nn + i] = s; d[i] = s;
        }
    }
    __syncthreads();
    for (int k = 2; k <= 2048; k <<= 1) {
        for (int j = k >> 1; j > 0; j >>= 1) {
            for (int i = t; i < 2048; i += 1024) {
                int l = i ^ j;
                if (l > i) {
                    bool up = ((i & k) == 0);
                    float a = d[i], c = d[l];
                    if ((a > c) == up) { d[i] = c; d[l] = a; }
                }
            }
            __syncthreads();
        }
    }
    if (t == 0) {
        if (which) g_rowth[b] = d[KTH];
        else       g_colth[b] = d[KTH];
    }
}

// ---------------- K7: final pass (no expf): masks, sparse weights, src_corr ----------------
__global__ __launch_bounds__(256) void k_final(const float* __restrict__ tgt, float* __restrict__ out) {
    int n = blockIdx.x, b = blockIdx.y;
    __shared__ float sv[Mm];
    __shared__ float red[256];
    int t = threadIdx.x;
    const float* row = g_pd + ((size_t)b * Nn + n) * Mm;   // holds E
    const float* csc = g_colscore + b * Mm;
    float ri   = g_rowinv[b * Nn + n];
    float topk = ri;   // argmax: E==1.0 exactly -> s==ri bitwise
    float maskSrc = (g_rowscore[b * Nn + n] < g_rowth[b]) ? 1.f : 0.f;
    float cth = g_colth[b];

    float lsum = 0.f;
#pragma unroll
    for (int k = 0; k < 2; k++) {
        int idx = t + k * 256;
        float4 e  = *(const float4*)&row[idx * 4];
        float4 c4 = *(const float4*)&csc[idx * 4];
        float w0, w1, w2, w3;
        {
            float s = e.x * ri;
            float o = maskSrc != 0.f ? 1.f : ((c4.x < cth) ? 1.f : 0.f);
            w0 = ((o + s) < topk) ? 0.f : s;
        }
        {
            float s = e.y * ri;
            float o = maskSrc != 0.f ? 1.f : ((c4.y < cth) ? 1.f : 0.f);
            w1 = ((o + s) < topk) ? 0.f : s;
        }
        {
            float s = e.z * ri;
            float o = maskSrc != 0.f ? 1.f : ((c4.z < cth) ? 1.f : 0.f);
            w2 = ((o + s) < topk) ? 0.f : s;
        }
        {
            float s = e.w * ri;
            float o = maskSrc != 0.f ? 1.f : ((c4.w < cth) ? 1.f : 0.f);
            w3 = ((o + s) < topk) ? 0.f : s;
        }
        int m4 = idx * 4;
        sv[m4] = w0; sv[m4+1] = w1; sv[m4+2] = w2; sv[m4+3] = w3;
        lsum += (w0 + w1) + (w2 + w3);
    }
    float cs = bsum256(lsum, red);
    cs = (cs < 1e-5f) ? 1e-5f : cs;
    float inv = 1.f / cs;

    const float* tg = tgt + (size_t)b * 3 * Mm;
    float a0 = 0.f, a1 = 0.f, a2 = 0.f, avs = 0.f;
    for (int k = 0; k < 2; k++) {
        int m4 = (t + k * 256) * 4;
#pragma unroll
        for (int q = 0; q < 4; q++) {
            float w = sv[m4 + q] * inv;
            avs += w;
            a0 += tg[m4 + q]          * w;
            a1 += tg[Mm + m4 + q]     * w;
            a2 += tg[2 * Mm + m4 + q] * w;
        }
    }
    a0  = bsum256(a0,  red);
    a1  = bsum256(a1,  red);
    a2  = bsum256(a2,  red);
    avs = bsum256(avs, red);
    if (t == 0) {
        out[OFF_CORR + (size_t)b * 3 * Nn + 0 * Nn + n] = a0;
        out[OFF_CORR + (size_t)b * 3 * Nn + 1 * Nn + n] = a1;
        out[OFF_CORR + (size_t)b * 3 * Nn + 2 * Nn + n] = a2;
        g_valsum[b * Nn + n] = (maskSrc != 0.f) ? 0.f : avs;
        out[OFF_MS + b * Nn + n] = maskSrc;
    }
}

// ---------------- K8: src_weight ----------------
__global__ void k_srcweight(float* __restrict__ out) {
    int b = blockIdx.x, t = threadIdx.x;  // 1024
    __shared__ float red[1024];
    float v0 = g_valsum[b * Nn + t];
    float v1 = g_valsum[b * Nn + t + 1024];
    red[t] = v0 + v1; __syncthreads();
#pragma unroll
    for (int s = 512; s > 0; s >>= 1) {
        if (t < s) red[t] += red[t + s];
        __syncthreads();
    }
    float tot = red[0];
    out[OFF_SW + b * Nn + t]        = v0 / tot;
    out[OFF_SW + b * Nn + t + 1024] = v1 / tot;
}

// ---------------- K9: mask_tgt ----------------
__global__ void k_masktgt(float* __restrict__ out) {
    int idx = blockIdx.x * 256 + threadIdx.x;
    if (idx >= Bz * Mm) return;
    int b = idx / Mm;
    out[OFF_MT + idx] = (g_colscore[idx] < g_colth[b]) ? 1.f : 0.f;
}

// ---------------- launch ----------------
extern "C" void kernel_launch(void* const* d_in, const int* in_sizes, int n_in,
                              void* d_out, int out_size) {
    const float* src_emb = (const float*)d_in[0];
    const float* tgt_emb = (const float*)d_in[1];
    const float* tgt     = (const float*)d_in[3];
    float* out = (float*)d_out;

    k_sq<<<(Bz*Nn + 255)/256, 256>>>(src_emb, Nn, 0);
    k_sq<<<(Bz*Mm + 255)/256, 256>>>(tgt_emb, Mm, 1);
    k_gemm<<<dim3(Mm/128, Nn/128, Bz), 256>>>(src_emb, tgt_emb);
    k_combine1<<<(2*Bz*Nn + 255)/256, 256>>>();
    k_cref<<<Bz, 1024>>>();
    k_sums<<<dim3(Mm/128, Nn/64, Bz), 256>>>();
    k_combine2<<<(2*Bz*Nn + 255)/256, 256>>>();
    k_scores<<<dim3(Mm/128, Nn/64, Bz), 256>>>();
    k_thresh<<<Bz*2, 1024>>>();
    k_final<<<dim3(Nn, Bz), 256>>>(tgt, out);
    k_srcweight<<<Bz, 1024>>>(out);
    k_masktgt<<<(Bz*Mm + 255)/256, 256>>>(out);
}